// round 2
// baseline (speedup 1.0000x reference)
#include <cuda_runtime.h>
#include <math.h>

#define NMAX 20000
#define EMAX 320000

// ---------------- device scratch (no allocations allowed) ----------------
__device__ float g_feat[(size_t)NMAX * 512];   // x @ W   -> [N, H=4, D=128]
__device__ float g_rst [(size_t)NMAX * 512];   // residual + bias + scatter acc
__device__ float g_h   [(size_t)NMAX * 128];   // dense layer output (layer input)
__device__ float g_el  [NMAX * 4];
__device__ float g_er  [NMAX * 4];
__device__ float g_m   [NMAX * 4];
__device__ float g_s   [NMAX * 4];
__device__ float g_ex  [EMAX * 4];

// ---------------- SGEMM: C[M,Nc] = op(A)[M,K] @ B[K,Nc] (+bias)(+relu) ----
// BM=BN=64, BK=16, 256 threads, 4x4 micro-tile per thread.
// Requires: K % 16 == 0, Nc % 64 == 0. M guarded.
template<bool RELU_A, bool ADD_BIAS, bool RELU_OUT>
__global__ void sgemm_kernel(const float* __restrict__ A,
                             const float* __restrict__ B,
                             const float* __restrict__ bias,
                             float* __restrict__ C,
                             int M, int Nc, int K)
{
    __shared__ float As[16][64];
    __shared__ float Bs[16][64];

    const int tid  = threadIdx.x;
    const int tx   = tid & 15;
    const int ty   = tid >> 4;
    const int row0 = blockIdx.y * 64;
    const int col0 = blockIdx.x * 64;

    const int aRow = tid >> 2;          // 0..63
    const int aCol = (tid & 3) << 2;    // 0,4,8,12
    const int bRow = tid >> 4;          // 0..15
    const int bCol = (tid & 15) << 2;   // 0..60

    float acc[4][4] = {};

    for (int k0 = 0; k0 < K; k0 += 16) {
        float4 av;
        const int arow = row0 + aRow;
        if (arow < M) {
            av = *(const float4*)(A + (size_t)arow * K + k0 + aCol);
        } else {
            av = make_float4(0.f, 0.f, 0.f, 0.f);
        }
        if (RELU_A) {
            av.x = fmaxf(av.x, 0.f); av.y = fmaxf(av.y, 0.f);
            av.z = fmaxf(av.z, 0.f); av.w = fmaxf(av.w, 0.f);
        }
        As[aCol + 0][aRow] = av.x;
        As[aCol + 1][aRow] = av.y;
        As[aCol + 2][aRow] = av.z;
        As[aCol + 3][aRow] = av.w;

        float4 bv = *(const float4*)(B + (size_t)(k0 + bRow) * Nc + col0 + bCol);
        *(float4*)&Bs[bRow][bCol] = bv;

        __syncthreads();

        #pragma unroll
        for (int k = 0; k < 16; k++) {
            float a4[4], b4[4];
            *(float4*)a4 = *(const float4*)&As[k][ty * 4];
            *(float4*)b4 = *(const float4*)&Bs[k][tx * 4];
            #pragma unroll
            for (int i = 0; i < 4; i++)
                #pragma unroll
                for (int j = 0; j < 4; j++)
                    acc[i][j] += a4[i] * b4[j];
        }
        __syncthreads();
    }

    #pragma unroll
    for (int i = 0; i < 4; i++) {
        const int r = row0 + ty * 4 + i;
        if (r >= M) continue;
        #pragma unroll
        for (int j = 0; j < 4; j++) {
            const int c = col0 + tx * 4 + j;
            float v = acc[i][j];
            if (ADD_BIAS) v += bias[c];
            if (RELU_OUT) v = fmaxf(v, 0.f);
            C[(size_t)r * Nc + c] = v;
        }
    }
}

// ---------------- attention logits: el/er per (node, head); init m/s ------
__global__ void eler_kernel(const float* __restrict__ feat,
                            const float* __restrict__ al,
                            const float* __restrict__ ar,
                            int N)
{
    const int g    = blockIdx.x * blockDim.x + threadIdx.x;
    const int w    = g >> 5;
    const int lane = g & 31;
    if (w >= N * 4) return;
    const int n = w >> 2, h = w & 3;

    float4 f = *(const float4*)(feat + (size_t)n * 512 + h * 128 + lane * 4);
    float4 a = *(const float4*)(al + h * 128 + lane * 4);
    float4 b = *(const float4*)(ar + h * 128 + lane * 4);
    float l = f.x * a.x + f.y * a.y + f.z * a.z + f.w * a.w;
    float r = f.x * b.x + f.y * b.y + f.z * b.z + f.w * b.w;
    #pragma unroll
    for (int o = 16; o > 0; o >>= 1) {
        l += __shfl_xor_sync(0xFFFFFFFFu, l, o);
        r += __shfl_xor_sync(0xFFFFFFFFu, r, o);
    }
    if (lane == 0) {
        g_el[w] = l;
        g_er[w] = r;
        g_m[w]  = __int_as_float(0xff800000);  // -inf
        g_s[w]  = 0.f;
    }
}

// ---------------- edge logits + atomic max per dst ------------------------
__global__ void edge_max_kernel(const int* __restrict__ src,
                                const int* __restrict__ dst, int E)
{
    const int i = blockIdx.x * blockDim.x + threadIdx.x;
    if (i >= E * 4) return;
    const int e = i >> 2, h = i & 3;
    const int sN = src[e], dN = dst[e];
    float v = g_el[sN * 4 + h] + g_er[dN * 4 + h];
    v = v > 0.f ? v : 0.2f * v;                // leaky_relu(0.2)
    g_ex[i] = v;
    float* addr = &g_m[dN * 4 + h];
    if (v >= 0.f) atomicMax((int*)addr, __float_as_int(v));
    else          atomicMin((unsigned int*)addr, __float_as_uint(v));
}

// ---------------- exp(e - m[dst]) + atomic sum per dst --------------------
__global__ void edge_exp_kernel(const int* __restrict__ dst, int E)
{
    const int i = blockIdx.x * blockDim.x + threadIdx.x;
    if (i >= E * 4) return;
    const int e = i >> 2, h = i & 3;
    const int dN = dst[e];
    const float v = expf(g_ex[i] - g_m[dN * 4 + h]);
    g_ex[i] = v;
    atomicAdd(&g_s[dN * 4 + h], v);
}

// ---------------- scatter: rst[dst] += alpha * feat[src] ------------------
// one warp per (edge, head); each lane handles 4 contiguous d's
__global__ void scatter_kernel(const int* __restrict__ src,
                               const int* __restrict__ dst, int E)
{
    const int g    = blockIdx.x * blockDim.x + threadIdx.x;
    const int w    = g >> 5;
    const int lane = g & 31;
    if (w >= E * 4) return;
    const int e = w >> 2, h = w & 3;
    const int sN = src[e], dN = dst[e];
    const float alpha = g_ex[w] / g_s[dN * 4 + h];

    float4 f = *(const float4*)(&g_feat[(size_t)sN * 512 + h * 128 + lane * 4]);
    float* o = &g_rst[(size_t)dN * 512 + h * 128 + lane * 4];
    atomicAdd(o + 0, alpha * f.x);
    atomicAdd(o + 1, alpha * f.y);
    atomicAdd(o + 2, alpha * f.z);
    atomicAdd(o + 3, alpha * f.w);
}

// ---------------- final: relu -> mean over heads -> relu -> max over nodes
__global__ void zero_out_kernel(float* out) { out[threadIdx.x] = 0.f; }

__global__ void final_kernel(float* __restrict__ out, int N)
{
    const int d = threadIdx.x;  // 0..127
    float mx = 0.f;
    for (int n = blockIdx.x; n < N; n += gridDim.x) {
        const float* r = &g_rst[(size_t)n * 512];
        float acc = fmaxf(r[d], 0.f) + fmaxf(r[128 + d], 0.f)
                  + fmaxf(r[256 + d], 0.f) + fmaxf(r[384 + d], 0.f);
        mx = fmaxf(mx, acc * 0.25f);
    }
    // values are >= 0, so int-compare atomicMax is order-correct
    atomicMax((int*)&out[d], __float_as_int(mx));
}

// ---------------- host-side orchestration ---------------------------------
static void run_gat_layer(const float* X,
                          const float* W, const float* al, const float* ar,
                          const float* b, const float* rW,
                          const int* src, const int* dst,
                          float* feat, float* rst, int N, int E)
{
    dim3 g1(512 / 64, (N + 63) / 64);
    sgemm_kernel<false, false, false><<<g1, 256>>>(X, W,  nullptr, feat, N, 512, 128);
    sgemm_kernel<false, true,  false><<<g1, 256>>>(X, rW, b,       rst,  N, 512, 128);

    const int nwarp = N * 4;
    eler_kernel<<<(nwarp * 32 + 255) / 256, 256>>>(feat, al, ar, N);
    edge_max_kernel<<<(E * 4 + 255) / 256, 256>>>(src, dst, E);
    edge_exp_kernel<<<(E * 4 + 255) / 256, 256>>>(dst, E);
    const long long sth = (long long)E * 4 * 32;
    scatter_kernel<<<(unsigned)((sth + 255) / 256), 256>>>(src, dst, E);
}

extern "C" void kernel_launch(void* const* d_in, const int* in_sizes, int n_in,
                              void* d_out, int out_size)
{
    const float* x   = (const float*)d_in[0];
    const int*   src = (const int*)  d_in[1];
    const int*   dst = (const int*)  d_in[2];
    const float* W0  = (const float*)d_in[3];
    const float* al0 = (const float*)d_in[4];
    const float* ar0 = (const float*)d_in[5];
    const float* b0  = (const float*)d_in[6];
    const float* rW0 = (const float*)d_in[7];
    const float* DW0 = (const float*)d_in[8];
    const float* Db0 = (const float*)d_in[9];
    const float* W1  = (const float*)d_in[10];
    const float* al1 = (const float*)d_in[11];
    const float* ar1 = (const float*)d_in[12];
    const float* b1  = (const float*)d_in[13];
    const float* rW1 = (const float*)d_in[14];
    const float* DW1 = (const float*)d_in[15];
    const float* Db1 = (const float*)d_in[16];
    const float* W2  = (const float*)d_in[17];
    const float* al2 = (const float*)d_in[18];
    const float* ar2 = (const float*)d_in[19];
    const float* b2  = (const float*)d_in[20];
    const float* rW2 = (const float*)d_in[21];

    const int N = in_sizes[0] / 128;
    const int E = in_sizes[1];

    float *feat, *rst, *h;
    cudaGetSymbolAddress((void**)&feat, g_feat);
    cudaGetSymbolAddress((void**)&rst,  g_rst);
    cudaGetSymbolAddress((void**)&h,    g_h);
    float* out = (float*)d_out;

    dim3 gd(128 / 64, (N + 63) / 64);

    // ---- layer 0 ----
    run_gat_layer(x, W0, al0, ar0, b0, rW0, src, dst, feat, rst, N, E);
    sgemm_kernel<true, true, true><<<gd, 256>>>(rst, DW0, Db0, h, N, 128, 512);

    // ---- layer 1 ----
    run_gat_layer(h, W1, al1, ar1, b1, rW1, src, dst, feat, rst, N, E);
    sgemm_kernel<true, true, true><<<gd, 256>>>(rst, DW1, Db1, h, N, 128, 512);

    // ---- layer 2 + pooling ----
    run_gat_layer(h, W2, al2, ar2, b2, rW2, src, dst, feat, rst, N, E);
    zero_out_kernel<<<1, 128>>>(out);
    final_kernel<<<256, 128>>>(out, N);
}

// round 4
// speedup vs baseline: 1.4117x; 1.4117x over previous
#include <cuda_runtime.h>
#include <math.h>

#define NMAX 20000
#define EMAX 320000

// ---------------- device scratch (no allocations allowed) ----------------
__device__ float g_feat[(size_t)NMAX * 512];   // x @ W   -> [N, H=4, D=128]
__device__ float g_rst [(size_t)NMAX * 512];   // residual + bias + scatter acc
__device__ float g_h   [(size_t)NMAX * 128];   // dense layer output (layer input)
__device__ float g_el  [NMAX * 4];
__device__ float g_er  [NMAX * 4];
__device__ float g_m   [NMAX * 4];
__device__ float g_s   [NMAX * 4];
__device__ float g_ex  [EMAX * 4];

// ---------------- SGEMM: C[M,Nc] = op(A)[M,K] @ B[K,Nc] (+bias)(+relu) ----
// BM=BN=128, BK=8, 256 threads, 8x8 micro-tile per thread.
// Requires: K % 8 == 0, Nc % 128 == 0. M guarded.
template<bool RELU_A, bool ADD_BIAS, bool RELU_OUT>
__global__ __launch_bounds__(256, 1)
void sgemm_kernel(const float* __restrict__ A,
                  const float* __restrict__ B,
                  const float* __restrict__ bias,
                  float* __restrict__ C,
                  int M, int Nc, int K)
{
    __shared__ float As[8][132];   // padded: transposed stores conflict-free
    __shared__ float Bs[8][128];

    const int tid  = threadIdx.x;
    const int tx   = tid & 15;     // 0..15 -> col group
    const int ty   = tid >> 4;     // 0..15 -> row group
    const int row0 = blockIdx.y * 128;
    const int col0 = blockIdx.x * 128;

    // A-load mapping: 128 rows x 8 cols; thread loads one float4
    const int aRow = tid >> 1;            // 0..127
    const int aCol = (tid & 1) << 2;      // 0 or 4
    // B-load mapping: 8 rows x 128 cols; thread loads one float4
    const int bRow = tid >> 5;            // 0..7
    const int bCol = (tid & 31) << 2;     // 0..124

    float acc[8][8] = {};

    const float* Aptr = A + (size_t)(row0 + aRow) * K + aCol;
    const bool  aOK   = (row0 + aRow) < M;

    for (int k0 = 0; k0 < K; k0 += 8) {
        float4 av = make_float4(0.f, 0.f, 0.f, 0.f);
        if (aOK) av = *(const float4*)(Aptr + k0);
        if (RELU_A) {
            av.x = fmaxf(av.x, 0.f); av.y = fmaxf(av.y, 0.f);
            av.z = fmaxf(av.z, 0.f); av.w = fmaxf(av.w, 0.f);
        }
        As[aCol + 0][aRow] = av.x;
        As[aCol + 1][aRow] = av.y;
        As[aCol + 2][aRow] = av.z;
        As[aCol + 3][aRow] = av.w;

        float4 bv = *(const float4*)(B + (size_t)(k0 + bRow) * Nc + col0 + bCol);
        *(float4*)&Bs[bRow][bCol] = bv;

        __syncthreads();

        #pragma unroll
        for (int k = 0; k < 8; k++) {
            float a8[8], b8[8];
            *(float4*)(a8 + 0) = *(const float4*)&As[k][ty * 8 + 0];
            *(float4*)(a8 + 4) = *(const float4*)&As[k][ty * 8 + 4];
            *(float4*)(b8 + 0) = *(const float4*)&Bs[k][tx * 8 + 0];
            *(float4*)(b8 + 4) = *(const float4*)&Bs[k][tx * 8 + 4];
            #pragma unroll
            for (int i = 0; i < 8; i++)
                #pragma unroll
                for (int j = 0; j < 8; j++)
                    acc[i][j] += a8[i] * b8[j];
        }
        __syncthreads();
    }

    // epilogue
    float bb[8];
    if (ADD_BIAS) {
        *(float4*)(bb + 0) = *(const float4*)(bias + col0 + tx * 8 + 0);
        *(float4*)(bb + 4) = *(const float4*)(bias + col0 + tx * 8 + 4);
    }
    #pragma unroll
    for (int i = 0; i < 8; i++) {
        const int r = row0 + ty * 8 + i;
        if (r >= M) continue;
        float4 o0, o1;
        float v[8];
        #pragma unroll
        for (int j = 0; j < 8; j++) {
            float t = acc[i][j];
            if (ADD_BIAS) t += bb[j];
            if (RELU_OUT) t = fmaxf(t, 0.f);
            v[j] = t;
        }
        o0 = make_float4(v[0], v[1], v[2], v[3]);
        o1 = make_float4(v[4], v[5], v[6], v[7]);
        float* cp = C + (size_t)r * Nc + col0 + tx * 8;
        *(float4*)(cp + 0) = o0;
        *(float4*)(cp + 4) = o1;
    }
}

// ---------------- attention logits: el/er per (node, head); init m/s ------
__global__ void eler_kernel(const float* __restrict__ feat,
                            const float* __restrict__ al,
                            const float* __restrict__ ar,
                            int N)
{
    const int g    = blockIdx.x * blockDim.x + threadIdx.x;
    const int w    = g >> 5;
    const int lane = g & 31;
    if (w >= N * 4) return;
    const int n = w >> 2, h = w & 3;

    float4 f = *(const float4*)(feat + (size_t)n * 512 + h * 128 + lane * 4);
    float4 a = *(const float4*)(al + h * 128 + lane * 4);
    float4 b = *(const float4*)(ar + h * 128 + lane * 4);
    float l = f.x * a.x + f.y * a.y + f.z * a.z + f.w * a.w;
    float r = f.x * b.x + f.y * b.y + f.z * b.z + f.w * b.w;
    #pragma unroll
    for (int o = 16; o > 0; o >>= 1) {
        l += __shfl_xor_sync(0xFFFFFFFFu, l, o);
        r += __shfl_xor_sync(0xFFFFFFFFu, r, o);
    }
    if (lane == 0) {
        g_el[w] = l;
        g_er[w] = r;
        g_m[w]  = __int_as_float(0xff800000);  // -inf
        g_s[w]  = 0.f;
    }
}

// ---------------- edge logits + atomic max per dst ------------------------
__global__ void edge_max_kernel(const int* __restrict__ src,
                                const int* __restrict__ dst, int E)
{
    const int i = blockIdx.x * blockDim.x + threadIdx.x;
    if (i >= E * 4) return;
    const int e = i >> 2, h = i & 3;
    const int sN = src[e], dN = dst[e];
    float v = g_el[sN * 4 + h] + g_er[dN * 4 + h];
    v = v > 0.f ? v : 0.2f * v;                // leaky_relu(0.2)
    g_ex[i] = v;
    float* addr = &g_m[dN * 4 + h];
    if (v >= 0.f) atomicMax((int*)addr, __float_as_int(v));
    else          atomicMin((unsigned int*)addr, __float_as_uint(v));
}

// ---------------- exp(e - m[dst]) + atomic sum per dst --------------------
__global__ void edge_exp_kernel(const int* __restrict__ dst, int E)
{
    const int i = blockIdx.x * blockDim.x + threadIdx.x;
    if (i >= E * 4) return;
    const int e = i >> 2, h = i & 3;
    const int dN = dst[e];
    const float v = expf(g_ex[i] - g_m[dN * 4 + h]);
    g_ex[i] = v;
    atomicAdd(&g_s[dN * 4 + h], v);
}

// ---------------- scatter: rst[dst] += alpha * feat[src] ------------------
// one warp per (edge, head); each lane handles one float4 -> vector red
__global__ void scatter_kernel(const int* __restrict__ src,
                               const int* __restrict__ dst, int E)
{
    const int g    = blockIdx.x * blockDim.x + threadIdx.x;
    const int w    = g >> 5;
    const int lane = g & 31;
    if (w >= E * 4) return;
    const int e = w >> 2, h = w & 3;
    const int sN = src[e], dN = dst[e];
    const float alpha = g_ex[w] / g_s[dN * 4 + h];

    float4 f = *(const float4*)(&g_feat[(size_t)sN * 512 + h * 128 + lane * 4]);
    float* o = &g_rst[(size_t)dN * 512 + h * 128 + lane * 4];
    asm volatile("red.global.add.v4.f32 [%0], {%1, %2, %3, %4};"
                 :: "l"(o), "f"(alpha * f.x), "f"(alpha * f.y),
                    "f"(alpha * f.z), "f"(alpha * f.w)
                 : "memory");
}

// ---------------- final: relu -> mean over heads -> relu -> max over nodes
__global__ void zero_out_kernel(float* out) { out[threadIdx.x] = 0.f; }

__global__ void final_kernel(float* __restrict__ out, int N)
{
    const int d = threadIdx.x;  // 0..127
    float mx = 0.f;
    for (int n = blockIdx.x; n < N; n += gridDim.x) {
        const float* r = &g_rst[(size_t)n * 512];
        float acc = fmaxf(r[d], 0.f) + fmaxf(r[128 + d], 0.f)
                  + fmaxf(r[256 + d], 0.f) + fmaxf(r[384 + d], 0.f);
        mx = fmaxf(mx, acc * 0.25f);
    }
    // values are >= 0, so int-compare atomicMax is order-correct
    atomicMax((int*)&out[d], __float_as_int(mx));
}

// ---------------- host-side orchestration ---------------------------------
static void run_gat_layer(const float* X,
                          const float* W, const float* al, const float* ar,
                          const float* b, const float* rW,
                          const int* src, const int* dst,
                          float* feat, float* rst, int N, int E)
{
    dim3 g1(512 / 128, (N + 127) / 128);
    sgemm_kernel<false, false, false><<<g1, 256>>>(X, W,  nullptr, feat, N, 512, 128);
    sgemm_kernel<false, true,  false><<<g1, 256>>>(X, rW, b,       rst,  N, 512, 128);

    const int nwarp = N * 4;
    eler_kernel<<<(nwarp * 32 + 255) / 256, 256>>>(feat, al, ar, N);
    edge_max_kernel<<<(E * 4 + 255) / 256, 256>>>(src, dst, E);
    edge_exp_kernel<<<(E * 4 + 255) / 256, 256>>>(dst, E);
    const long long sth = (long long)E * 4 * 32;
    scatter_kernel<<<(unsigned)((sth + 255) / 256), 256>>>(src, dst, E);
}

extern "C" void kernel_launch(void* const* d_in, const int* in_sizes, int n_in,
                              void* d_out, int out_size)
{
    const float* x   = (const float*)d_in[0];
    const int*   src = (const int*)  d_in[1];
    const int*   dst = (const int*)  d_in[2];
    const float* W0  = (const float*)d_in[3];
    const float* al0 = (const float*)d_in[4];
    const float* ar0 = (const float*)d_in[5];
    const float* b0  = (const float*)d_in[6];
    const float* rW0 = (const float*)d_in[7];
    const float* DW0 = (const float*)d_in[8];
    const float* Db0 = (const float*)d_in[9];
    const float* W1  = (const float*)d_in[10];
    const float* al1 = (const float*)d_in[11];
    const float* ar1 = (const float*)d_in[12];
    const float* b1  = (const float*)d_in[13];
    const float* rW1 = (const float*)d_in[14];
    const float* DW1 = (const float*)d_in[15];
    const float* Db1 = (const float*)d_in[16];
    const float* W2  = (const float*)d_in[17];
    const float* al2 = (const float*)d_in[18];
    const float* ar2 = (const float*)d_in[19];
    const float* b2  = (const float*)d_in[20];
    const float* rW2 = (const float*)d_in[21];

    const int N = in_sizes[0] / 128;
    const int E = in_sizes[1];

    float *feat, *rst, *h;
    cudaGetSymbolAddress((void**)&feat, g_feat);
    cudaGetSymbolAddress((void**)&rst,  g_rst);
    cudaGetSymbolAddress((void**)&h,    g_h);
    float* out = (float*)d_out;

    dim3 gd(128 / 128, (N + 127) / 128);

    // ---- layer 0 ----
    run_gat_layer(x, W0, al0, ar0, b0, rW0, src, dst, feat, rst, N, E);
    sgemm_kernel<true, true, true><<<gd, 256>>>(rst, DW0, Db0, h, N, 128, 512);

    // ---- layer 1 ----
    run_gat_layer(h, W1, al1, ar1, b1, rW1, src, dst, feat, rst, N, E);
    sgemm_kernel<true, true, true><<<gd, 256>>>(rst, DW1, Db1, h, N, 128, 512);

    // ---- layer 2 + pooling ----
    run_gat_layer(h, W2, al2, ar2, b2, rW2, src, dst, feat, rst, N, E);
    zero_out_kernel<<<1, 128>>>(out);
    final_kernel<<<256, 128>>>(out, N);
}